// round 17
// baseline (speedup 1.0000x reference)
#include <cuda_runtime.h>
#include <math.h>

#define IMG 256
#define NJ 21
#define NB 64
#define NIMG (NB * NJ)              // 1344
#define IMG_ELEMS (IMG * IMG)       // 65536
#define F4_PER_IMG (IMG_ELEMS / 4)  // 16384
#define ROWS_PER_BLOCK 32
#define BLOCKS_PER_IMG (IMG / ROWS_PER_BLOCK)       // 8
#define F4_PER_BLOCK (ROWS_PER_BLOCK * IMG / 4)     // 2048 -> 8 per thread @256

// ---------------------------------------------------------------------------
// Each block owns a 32-row slab of one (b, j) image.
//
// Order of operations is the whole point:
//   1) all 256 threads fire 8 streaming zero-stores immediately (no data
//      dependency -> store stream saturates from cycle 0)
//   2) thread 0 alone computes the fisheye projection, broadcasts (cx, cy)
//      through shared memory
//   3) after __syncthreads(), threads 0..120 overwrite their gaussian tap
//      if it falls inside this slab (WAW across the CTA barrier is ordered)
// ---------------------------------------------------------------------------
__global__ void __launch_bounds__(256) fused_kernel(const float* __restrict__ joint,
                                                    float4* __restrict__ out4) {
    const int blk = blockIdx.x;
    const int img = blk >> 3;                       // blk / BLOCKS_PER_IMG
    const int rowbase = (blk & 7) * ROWS_PER_BLOCK; // slab start row

    float4* __restrict__ base =
        out4 + (size_t)img * F4_PER_IMG + (size_t)rowbase * (IMG / 4);
    const int t = threadIdx.x;
    const float4 zero4 = make_float4(0.f, 0.f, 0.f, 0.f);

    // ---- 1) unconditional streaming zero-fill: 8 x 16B per thread ----
    float4* p = base + t;
    #pragma unroll
    for (int k = 0; k < 8; k++) __stcs(p + k * 256, zero4);

    // ---- 2) projection once per block ----
    __shared__ int s_cx, s_cy;
    if (t == 0) {
        const float x = joint[img * 3 + 0];
        const float y = joint[img * 3 + 1];
        const float z = joint[img * 3 + 2];

        const float theta = atan2f(sqrtf(x * x + y * y), z);
        const float phi   = atan2f(y, x);
        const float r     = (128.0f * theta) / 1.5707963267948966f;  // RADIUS*theta/(pi/2)

        // jnp.round == round-half-to-even == rintf
        int cx = (int)rintf(128.0f + r * cosf(phi));
        int cy = (int)rintf(128.0f + r * sinf(phi));
        s_cx = min(max(cx, 0), IMG - 1);
        s_cy = min(max(cy, 0), IMG - 1);
    }
    __syncthreads();

    // ---- 3) stamp overwrite: one tap per thread (0..120) ----
    if (t < 121) {
        const int dy = t / 11 - 5;
        const int dx = t % 11 - 5;
        const int py = s_cy + dy;
        const int px = s_cx + dx;
        // py in slab  =>  py in [0, 255] automatically (rowbase in [0, 224])
        if (py >= rowbase && py < rowbase + ROWS_PER_BLOCK && px >= 0 && px < IMG) {
            // peak-to-one gaussian: exp(-(dx^2+dy^2) / (2 * 2.5^2))
            const float w = expf(-(float)(dx * dx + dy * dy) * (1.0f / 12.5f));
            ((float*)base)[(py - rowbase) * IMG + px] = w;
        }
    }
}

extern "C" void kernel_launch(void* const* d_in, const int* in_sizes, int n_in,
                              void* d_out, int out_size) {
    const float* joint = (const float*)d_in[0];   // [64, 21, 3] f32
    float* out = (float*)d_out;                   // [64, 21, 256, 256] f32

    fused_kernel<<<NIMG * BLOCKS_PER_IMG, 256>>>(joint, (float4*)out);
}